// round 14
// baseline (speedup 1.0000x reference)
#include <cuda_runtime.h>
#include <cuda_bf16.h>
#include <math.h>
#include <stdint.h>

#define D_MODEL   1536
#define NUM_HEADS 16
#define QGROUPS   4
#define HEAD_DIM  96
#define QKV_OUT   2304      // 16*96 + 2*4*96
#define B_SZ      2
#define N_TOK     2048
#define BN_TOK    (B_SZ * N_TOK)

// ---------------- scratch (no allocations allowed) ----------------
__device__ float g_qkv [(size_t)BN_TOK * QKV_OUT];   // ~37.7 MB
__device__ float g_attn[(size_t)BN_TOK * D_MODEL];   // ~25.2 MB

__device__ __forceinline__ float tf32r(float x) {
    uint32_t u;
    asm("cvt.rna.tf32.f32 %0, %1;" : "=r"(u) : "f"(x));
    return __uint_as_float(u);
}
__device__ __forceinline__ void mma_tf32(float* c, const uint32_t* a, const uint32_t* b) {
    asm volatile(
        "mma.sync.aligned.m16n8k8.row.col.f32.tf32.tf32.f32 "
        "{%0,%1,%2,%3}, {%4,%5,%6,%7}, {%8,%9}, {%0,%1,%2,%3};"
        : "+f"(c[0]), "+f"(c[1]), "+f"(c[2]), "+f"(c[3])
        : "r"(a[0]), "r"(a[1]), "r"(a[2]), "r"(a[3]), "r"(b[0]), "r"(b[1]));
}
__device__ __forceinline__ void mma_bf16(float* c, const uint32_t* a,
                                         uint32_t b0, uint32_t b1) {
    asm volatile(
        "mma.sync.aligned.m16n8k16.row.col.f32.bf16.bf16.f32 "
        "{%0,%1,%2,%3}, {%4,%5,%6,%7}, {%8,%9}, {%0,%1,%2,%3};"
        : "+f"(c[0]), "+f"(c[1]), "+f"(c[2]), "+f"(c[3])
        : "r"(a[0]), "r"(a[1]), "r"(a[2]), "r"(a[3]), "r"(b0), "r"(b1));
}
// split (a,b) into packed bf16x2 hi and lo parts; a -> low half (lower k index)
__device__ __forceinline__ void bsplit2(float a, float b, uint32_t& hi, uint32_t& lo) {
    __nv_bfloat16 ah = __float2bfloat16_rn(a);
    __nv_bfloat16 bh = __float2bfloat16_rn(b);
    float ar = a - __bfloat162float(ah);
    float br = b - __bfloat162float(bh);
    __nv_bfloat162 h; h.x = ah; h.y = bh;
    __nv_bfloat162 l; l.x = __float2bfloat16_rn(ar); l.y = __float2bfloat16_rn(br);
    hi = *(uint32_t*)&h;
    lo = *(uint32_t*)&l;
}

// =====================================================================
// mma.sync tf32 GEMM (NT): C[M,N] = A[M,K] * B[N,K]^T, K-major rows.
// Block 128x128, BK=16, 256 threads = 8 warps (2M x 4N), warp = 64x32.
// 3-term tf32 hi/lo split. Software-pipelined: next tile's LDG issued
// right after STS so GMEM latency overlaps MMA compute.
// =====================================================================
#define BM 128
#define BN 128
#define BKK 16
__global__ __launch_bounds__(256, 2) void gemm_mma(const float* __restrict__ A,
                                                   const float* __restrict__ B,
                                                   float* __restrict__ C,
                                                   int M, int N, int K) {
    __shared__ float2 Ah[2][16][32];
    __shared__ float2 Al[2][16][32];
    __shared__ float2 Bh[2][16][32];
    __shared__ float2 Bl[2][16][32];

    const int tid   = threadIdx.x;
    const int lane  = tid & 31;
    const int w     = tid >> 5;
    const int warpM = w >> 2;          // 0..1
    const int warpN = w & 3;           // 0..3
    const int bm    = blockIdx.y * BM;
    const int bn    = blockIdx.x * BN;

    float acc[4][4][4];
#pragma unroll
    for (int t = 0; t < 4; t++)
#pragma unroll
        for (int u = 0; u < 4; u++)
#pragma unroll
            for (int q = 0; q < 4; q++) acc[t][u][q] = 0.f;

    const float* Ab = A + (size_t)bm * K;
    const float* Bb = B + (size_t)bn * K;

    // prologue: stage first tile
    float4 av[2], bv[2];
#pragma unroll
    for (int j = 0; j < 2; j++) {
        int idx = tid + 256 * j;
        int r = idx >> 2, c4 = idx & 3;
        av[j] = *(const float4*)(Ab + (size_t)r * K + c4 * 4);
        bv[j] = *(const float4*)(Bb + (size_t)r * K + c4 * 4);
    }

    for (int kt = 0; kt < K; kt += BKK) {
        __syncthreads();   // previous compute done reading fragments

        // ---- split to tf32 hi/lo, store fragments ----
#pragma unroll
        for (int j = 0; j < 2; j++) {
            int idx = tid + 256 * j;
            int r = idx >> 2, c4 = idx & 3;
            int h    = c4 >> 1;
            int comp = c4 & 1;
            int rg   = r >> 3;
            int lb   = (r & 7) * 4;
            float va[4] = {av[j].x, av[j].y, av[j].z, av[j].w};
            float vb[4] = {bv[j].x, bv[j].y, bv[j].z, bv[j].w};
#pragma unroll
            for (int q = 0; q < 4; q++) {
                float ahv = tf32r(va[q]);
                float alv = tf32r(va[q] - ahv);
                float bhv = tf32r(vb[q]);
                float blv = tf32r(vb[q] - bhv);
                ((float*)&Ah[h][rg][lb + q])[comp] = ahv;
                ((float*)&Al[h][rg][lb + q])[comp] = alv;
                ((float*)&Bh[h][rg][lb + q])[comp] = bhv;
                ((float*)&Bl[h][rg][lb + q])[comp] = blv;
            }
        }
        __syncthreads();

        // ---- prefetch next tile (overlaps with compute below) ----
        if (kt + BKK < K) {
#pragma unroll
            for (int j = 0; j < 2; j++) {
                int idx = tid + 256 * j;
                int r = idx >> 2, c4 = idx & 3;
                av[j] = *(const float4*)(Ab + (size_t)r * K + kt + BKK + c4 * 4);
                bv[j] = *(const float4*)(Bb + (size_t)r * K + kt + BKK + c4 * 4);
            }
        }

        // ---- compute ----
#pragma unroll
        for (int h = 0; h < 2; h++) {
            uint32_t ah[4][4], al[4][4];
            uint32_t bh[4][2], bl[4][2];
#pragma unroll
            for (int t = 0; t < 4; t++) {
                int g0 = (warpM * 4 + t) * 2;
                float2 p0 = Ah[h][g0][lane];
                float2 p1 = Ah[h][g0 + 1][lane];
                ah[t][0] = __float_as_uint(p0.x); ah[t][1] = __float_as_uint(p1.x);
                ah[t][2] = __float_as_uint(p0.y); ah[t][3] = __float_as_uint(p1.y);
                float2 q0 = Al[h][g0][lane];
                float2 q1 = Al[h][g0 + 1][lane];
                al[t][0] = __float_as_uint(q0.x); al[t][1] = __float_as_uint(q1.x);
                al[t][2] = __float_as_uint(q0.y); al[t][3] = __float_as_uint(q1.y);
            }
#pragma unroll
            for (int u = 0; u < 4; u++) {
                float2 p = Bh[h][warpN * 4 + u][lane];
                bh[u][0] = __float_as_uint(p.x); bh[u][1] = __float_as_uint(p.y);
                float2 q = Bl[h][warpN * 4 + u][lane];
                bl[u][0] = __float_as_uint(q.x); bl[u][1] = __float_as_uint(q.y);
            }
#pragma unroll
            for (int t = 0; t < 4; t++)
#pragma unroll
                for (int u = 0; u < 4; u++) {
                    mma_tf32(acc[t][u], ah[t], bh[u]);
                    mma_tf32(acc[t][u], ah[t], bl[u]);
                    mma_tf32(acc[t][u], al[t], bh[u]);
                }
        }
    }

    const int g = lane >> 2, q2 = (lane & 3) * 2;
#pragma unroll
    for (int t = 0; t < 4; t++) {
        int m0 = bm + warpM * 64 + t * 16 + g;
#pragma unroll
        for (int u = 0; u < 4; u++) {
            int n0 = bn + warpN * 32 + u * 8 + q2;
            *(float2*)(C + (size_t)m0 * N + n0)       = make_float2(acc[t][u][0], acc[t][u][1]);
            *(float2*)(C + (size_t)(m0 + 8) * N + n0) = make_float2(acc[t][u][2], acc[t][u][3]);
        }
    }
}

// =====================================================================
// RoPE-3D applied in place to Q (16 heads) and K (4 groups) of g_qkv.
// =====================================================================
__global__ void rope_kernel(const int* __restrict__ pgt,
                            const int* __restrict__ pgh,
                            const int* __restrict__ pgw) {
    const int token = blockIdx.x;
    const int GH = *pgh, GW = *pgw;
    const int n = token % N_TOK;
    int posv[3];
    posv[0] = n / (GH * GW);
    posv[1] = (n / GW) % GH;
    posv[2] = n % GW;

    const size_t base = (size_t)token * QKV_OUT;
    for (int idx = threadIdx.x; idx < 20 * 48; idx += blockDim.x) {
        const int head = idx / 48;
        const int pi   = idx % 48;
        const int axis = pi >> 4;
        const int p    = pi & 15;
        float freq = powf(10000.0f, -(float)p / 16.0f);
        float ang  = (float)posv[axis] * freq;
        float s, c;
        sincosf(ang, &s, &c);
        int off = (head < 16) ? (head * HEAD_DIM + axis * 32 + 2 * p)
                              : (1536 + (head - 16) * HEAD_DIM + axis * 32 + 2 * p);
        float x0 = g_qkv[base + off];
        float x1 = g_qkv[base + off + 1];
        g_qkv[base + off]     = x0 * c - x1 * s;
        g_qkv[base + off + 1] = x0 * s + x1 * c;
    }
}

// =====================================================================
// Flash attention via mma.sync bf16 (3-term hi/lo split).
// CTA = (64 q-rows, head, batch), 4 warps, warp = 16 q-rows.
// Q fragments in registers (scale folded); K/V packed bf16 fragments in
// SMEM built directly from gmem; P fragments straight from S accumulators.
// =====================================================================
__global__ __launch_bounds__(128, 2) void attn_mma() {
    __shared__ uint4 Kf[6][8][32];    // [k16 step][n8 chunk][lane] = {b0h,b1h,b0l,b1l}
    __shared__ uint4 Vf[4][12][32];   // [k16 step][n8 chunk][lane]

    const int tid  = threadIdx.x;
    const int lane = tid & 31;
    const int w    = tid >> 5;        // 0..3
    const int lq   = lane & 3;
    const int lg   = lane >> 2;
    const int qtile = blockIdx.x;     // 0..31
    const int hh    = blockIdx.y;     // 0..15
    const int b     = blockIdx.z;     // 0..1
    const int kvg   = hh >> 2;

    const int koff = 1536 + kvg * HEAD_DIM;
    const int voff = 1920 + kvg * HEAD_DIM;
    const float scale = rsqrtf((float)HEAD_DIM);

    // ---- Q fragments (registers), scale folded in ----
    uint32_t QfH[6][4], QfL[6][4];
    {
        const int qrow = b * N_TOK + qtile * 64 + w * 16 + lg;
        const float* qp0 = g_qkv + (size_t)qrow * QKV_OUT + hh * HEAD_DIM;
        const float* qp1 = qp0 + (size_t)8 * QKV_OUT;
#pragma unroll
        for (int ks = 0; ks < 6; ks++) {
            float2 v0 = *(const float2*)(qp0 + 16 * ks + 2 * lq);
            float2 v1 = *(const float2*)(qp1 + 16 * ks + 2 * lq);
            float2 v2 = *(const float2*)(qp0 + 16 * ks + 2 * lq + 8);
            float2 v3 = *(const float2*)(qp1 + 16 * ks + 2 * lq + 8);
            bsplit2(v0.x * scale, v0.y * scale, QfH[ks][0], QfL[ks][0]);
            bsplit2(v1.x * scale, v1.y * scale, QfH[ks][1], QfL[ks][1]);
            bsplit2(v2.x * scale, v2.y * scale, QfH[ks][2], QfL[ks][2]);
            bsplit2(v3.x * scale, v3.y * scale, QfH[ks][3], QfL[ks][3]);
        }
    }

    float m0 = -INFINITY, m1 = -INFINITY, l0 = 0.f, l1 = 0.f;
    float oacc[12][4];
#pragma unroll
    for (int ch = 0; ch < 12; ch++)
#pragma unroll
        for (int q = 0; q < 4; q++) oacc[ch][q] = 0.f;

    for (int jt = 0; jt < N_TOK / 64; jt++) {
        const int kvtok = b * N_TOK + jt * 64;

        __syncthreads();   // previous compute done reading fragments

        // ---- build K fragments (1536 slots, 12 per thread) ----
        for (int s = tid; s < 6 * 8 * 32; s += 128) {
            int ks  = s >> 8;
            int rem = s & 255;
            int ch  = rem >> 5;
            int ln  = rem & 31;
            int n   = ch * 8 + (ln >> 2);
            int k0  = 2 * (ln & 3);
            const float* kp = g_qkv + (size_t)(kvtok + n) * QKV_OUT + koff + 16 * ks + k0;
            float2 p0 = *(const float2*)kp;
            float2 p1 = *(const float2*)(kp + 8);
            uint32_t b0h, b0l, b1h, b1l;
            bsplit2(p0.x, p0.y, b0h, b0l);
            bsplit2(p1.x, p1.y, b1h, b1l);
            Kf[ks][ch][ln] = make_uint4(b0h, b1h, b0l, b1l);
        }
        // ---- build V fragments (1536 slots, 12 per thread) ----
        for (int s = tid; s < 4 * 12 * 32; s += 128) {
            int ks  = s / 384;
            int rem = s % 384;
            int ch  = rem >> 5;
            int ln  = rem & 31;
            int n   = ch * 8 + (ln >> 2);        // head-dim col
            int k0  = 16 * ks + 2 * (ln & 3);    // kv row within tile
            const float* vp = g_qkv + (size_t)(kvtok + k0) * QKV_OUT + voff + n;
            float a0 = vp[0];
            float a1 = vp[QKV_OUT];
            float a2 = vp[(size_t)8 * QKV_OUT];
            float a3 = vp[(size_t)9 * QKV_OUT];
            uint32_t b0h, b0l, b1h, b1l;
            bsplit2(a0, a1, b0h, b0l);
            bsplit2(a2, a3, b1h, b1l);
            Vf[ks][ch][ln] = make_uint4(b0h, b1h, b0l, b1l);
        }
        __syncthreads();

        // ---- S = (Q*scale) K^T : 8 chunks x 6 ksteps x 3 terms ----
        float sacc[8][4];
#pragma unroll
        for (int ch = 0; ch < 8; ch++)
#pragma unroll
            for (int q = 0; q < 4; q++) sacc[ch][q] = 0.f;
#pragma unroll
        for (int ks = 0; ks < 6; ks++)
#pragma unroll
            for (int ch = 0; ch < 8; ch++) {
                uint4 kf = Kf[ks][ch][lane];
                mma_bf16(sacc[ch], QfH[ks], kf.x, kf.y);   // hi*hi
                mma_bf16(sacc[ch], QfH[ks], kf.z, kf.w);   // hi*lo
                mma_bf16(sacc[ch], QfL[ks], kf.x, kf.y);   // lo*hi
            }

        // ---- online softmax ----
        float mx0 = -INFINITY, mx1 = -INFINITY;
#pragma unroll
        for (int ch = 0; ch < 8; ch++) {
            mx0 = fmaxf(mx0, fmaxf(sacc[ch][0], sacc[ch][1]));
            mx1 = fmaxf(mx1, fmaxf(sacc[ch][2], sacc[ch][3]));
        }
        mx0 = fmaxf(mx0, __shfl_xor_sync(0xffffffffu, mx0, 1));
        mx0 = fmaxf(mx0, __shfl_xor_sync(0xffffffffu, mx0, 2));
        mx1 = fmaxf(mx1, __shfl_xor_sync(0xffffffffu, mx1, 1));
        mx1 = fmaxf(mx1, __shfl_xor_sync(0xffffffffu, mx1, 2));
        float mn0 = fmaxf(m0, mx0), mn1 = fmaxf(m1, mx1);
        float alpha0 = __expf(m0 - mn0), alpha1 = __expf(m1 - mn1);
        m0 = mn0; m1 = mn1;
        float sum0 = 0.f, sum1 = 0.f;
#pragma unroll
        for (int ch = 0; ch < 8; ch++) {
            sacc[ch][0] = __expf(sacc[ch][0] - mn0);
            sacc[ch][1] = __expf(sacc[ch][1] - mn0);
            sacc[ch][2] = __expf(sacc[ch][2] - mn1);
            sacc[ch][3] = __expf(sacc[ch][3] - mn1);
            sum0 += sacc[ch][0] + sacc[ch][1];
            sum1 += sacc[ch][2] + sacc[ch][3];
        }
        sum0 += __shfl_xor_sync(0xffffffffu, sum0, 1);
        sum0 += __shfl_xor_sync(0xffffffffu, sum0, 2);
        sum1 += __shfl_xor_sync(0xffffffffu, sum1, 1);
        sum1 += __shfl_xor_sync(0xffffffffu, sum1, 2);
        l0 = l0 * alpha0 + sum0;
        l1 = l1 * alpha1 + sum1;
#pragma unroll
        for (int ch = 0; ch < 12; ch++) {
            oacc[ch][0] *= alpha0; oacc[ch][1] *= alpha0;
            oacc[ch][2] *= alpha1; oacc[ch][3] *= alpha1;
        }

        // ---- O += P V : P fragments straight from sacc registers ----
#pragma unroll
        for (int c = 0; c < 4; c++) {
            uint32_t ph[4], pl[4];
            bsplit2(sacc[2 * c][0],     sacc[2 * c][1],     ph[0], pl[0]);
            bsplit2(sacc[2 * c][2],     sacc[2 * c][3],     ph[1], pl[1]);
            bsplit2(sacc[2 * c + 1][0], sacc[2 * c + 1][1], ph[2], pl[2]);
            bsplit2(sacc[2 * c + 1][2], sacc[2 * c + 1][3], ph[3], pl[3]);
#pragma unroll
            for (int ch = 0; ch < 12; ch++) {
                uint4 vf = Vf[c][ch][lane];
                mma_bf16(oacc[ch], ph, vf.x, vf.y);   // hi*hi
                mma_bf16(oacc[ch], ph, vf.z, vf.w);   // hi*lo
                mma_bf16(oacc[ch], pl, vf.x, vf.y);   // lo*hi
            }
        }
    }

    // ---- epilogue: normalize, write [b,n,h,d] ----
    {
        float inv0 = 1.f / l0, inv1 = 1.f / l1;
        const int orow = b * N_TOK + qtile * 64 + w * 16 + lg;
        float* op0 = g_attn + (size_t)orow * D_MODEL + hh * HEAD_DIM;
        float* op1 = op0 + (size_t)8 * D_MODEL;
#pragma unroll
        for (int ch = 0; ch < 12; ch++) {
            *(float2*)(op0 + 8 * ch + 2 * lq) = make_float2(oacc[ch][0] * inv0, oacc[ch][1] * inv0);
            *(float2*)(op1 + 8 * ch + 2 * lq) = make_float2(oacc[ch][2] * inv1, oacc[ch][3] * inv1);
        }
    }
}

// =====================================================================
extern "C" void kernel_launch(void* const* d_in, const int* in_sizes, int n_in,
                              void* d_out, int out_size) {
    const float* x     = (const float*)d_in[0];
    const float* w_qkv = (const float*)d_in[1];
    const float* w_o   = (const float*)d_in[2];
    const int*   gt    = (const int*)d_in[3];
    const int*   gh    = (const int*)d_in[4];
    const int*   gw    = (const int*)d_in[5];
    float* out = (float*)d_out;
    (void)in_sizes; (void)n_in; (void)out_size; (void)gt;

    float *qkv_ptr, *attn_ptr;
    cudaGetSymbolAddress((void**)&qkv_ptr,  g_qkv);
    cudaGetSymbolAddress((void**)&attn_ptr, g_attn);

    // 1) QKV projection: [4096,1536] @ [2304,1536]^T  (mma.sync tf32 3-term, pipelined)
    gemm_mma<<<dim3(QKV_OUT / BN, BN_TOK / BM), 256>>>(
        x, w_qkv, qkv_ptr, BN_TOK, QKV_OUT, D_MODEL);

    // 2) RoPE-3D in place on Q and K
    rope_kernel<<<BN_TOK, 128>>>(gt, gh, gw);

    // 3) GQA flash attention (mma.sync bf16 3-term) -> g_attn [4096,1536]
    attn_mma<<<dim3(N_TOK / 64, NUM_HEADS, B_SZ), 128>>>();

    // 4) Output projection: [4096,1536] @ [1536,1536]^T -> d_out (mma.sync tf32)
    gemm_mma<<<dim3(D_MODEL / BN, BN_TOK / BM), 256>>>(
        attn_ptr, w_o, out, BN_TOK, D_MODEL, D_MODEL);
}

// round 16
// speedup vs baseline: 1.8725x; 1.8725x over previous
#include <cuda_runtime.h>
#include <cuda_bf16.h>
#include <math.h>
#include <stdint.h>

#define D_MODEL   1536
#define NUM_HEADS 16
#define QGROUPS   4
#define HEAD_DIM  96
#define QKV_OUT   2304      // 16*96 + 2*4*96
#define B_SZ      2
#define N_TOK     2048
#define BN_TOK    (B_SZ * N_TOK)
#define KV_TILES  (N_TOK / 64)          // 32
#define KFRAG_PER_TILE 1536             // 6*8*32
#define VFRAG_PER_TILE 1536             // 4*12*32

// ---------------- scratch (no allocations allowed) ----------------
__device__ float g_qkv [(size_t)BN_TOK * QKV_OUT];   // ~37.7 MB
__device__ float g_attn[(size_t)BN_TOK * D_MODEL];   // ~25.2 MB
__device__ uint4 g_kfrag[(size_t)B_SZ * QGROUPS * KV_TILES * KFRAG_PER_TILE]; // 6.3 MB
__device__ uint4 g_vfrag[(size_t)B_SZ * QGROUPS * KV_TILES * VFRAG_PER_TILE]; // 6.3 MB

__device__ __forceinline__ float tf32r(float x) {
    uint32_t u;
    asm("cvt.rna.tf32.f32 %0, %1;" : "=r"(u) : "f"(x));
    return __uint_as_float(u);
}
__device__ __forceinline__ void mma_tf32(float* c, const uint32_t* a, const uint32_t* b) {
    asm volatile(
        "mma.sync.aligned.m16n8k8.row.col.f32.tf32.tf32.f32 "
        "{%0,%1,%2,%3}, {%4,%5,%6,%7}, {%8,%9}, {%0,%1,%2,%3};"
        : "+f"(c[0]), "+f"(c[1]), "+f"(c[2]), "+f"(c[3])
        : "r"(a[0]), "r"(a[1]), "r"(a[2]), "r"(a[3]), "r"(b[0]), "r"(b[1]));
}
__device__ __forceinline__ void mma_bf16(float* c, const uint32_t* a,
                                         uint32_t b0, uint32_t b1) {
    asm volatile(
        "mma.sync.aligned.m16n8k16.row.col.f32.bf16.bf16.f32 "
        "{%0,%1,%2,%3}, {%4,%5,%6,%7}, {%8,%9}, {%0,%1,%2,%3};"
        : "+f"(c[0]), "+f"(c[1]), "+f"(c[2]), "+f"(c[3])
        : "r"(a[0]), "r"(a[1]), "r"(a[2]), "r"(a[3]), "r"(b0), "r"(b1));
}
// split (a,b) into packed bf16x2 hi and lo parts; a -> low half (lower k index)
__device__ __forceinline__ void bsplit2(float a, float b, uint32_t& hi, uint32_t& lo) {
    __nv_bfloat16 ah = __float2bfloat16_rn(a);
    __nv_bfloat16 bh = __float2bfloat16_rn(b);
    float ar = a - __bfloat162float(ah);
    float br = b - __bfloat162float(bh);
    __nv_bfloat162 h; h.x = ah; h.y = bh;
    __nv_bfloat162 l; l.x = __float2bfloat16_rn(ar); l.y = __float2bfloat16_rn(br);
    hi = *(uint32_t*)&h;
    lo = *(uint32_t*)&l;
}

// =====================================================================
// mma.sync tf32 GEMM (NT) — exact R7 silicon-verified structure.
// Block 128x128, BK=16, 256 threads = 8 warps (2M x 4N), warp = 64x32.
// 3-term tf32 hi/lo split.
// =====================================================================
#define BM 128
#define BN 128
#define BKK 16
__global__ __launch_bounds__(256, 2) void gemm_mma(const float* __restrict__ A,
                                                   const float* __restrict__ B,
                                                   float* __restrict__ C,
                                                   int M, int N, int K) {
    __shared__ float2 Ah[2][16][32];
    __shared__ float2 Al[2][16][32];
    __shared__ float2 Bh[2][16][32];
    __shared__ float2 Bl[2][16][32];

    const int tid   = threadIdx.x;
    const int lane  = tid & 31;
    const int w     = tid >> 5;
    const int warpM = w >> 2;          // 0..1
    const int warpN = w & 3;           // 0..3
    const int bm    = blockIdx.y * BM;
    const int bn    = blockIdx.x * BN;

    float acc[4][4][4];
#pragma unroll
    for (int t = 0; t < 4; t++)
#pragma unroll
        for (int u = 0; u < 4; u++)
#pragma unroll
            for (int q = 0; q < 4; q++) acc[t][u][q] = 0.f;

    const float* Ab = A + (size_t)bm * K;
    const float* Bb = B + (size_t)bn * K;

    for (int kt = 0; kt < K; kt += BKK) {
        // ---- stage gmem -> regs (before overwriting smem) ----
        float4 av[2], bv[2];
#pragma unroll
        for (int j = 0; j < 2; j++) {
            int idx = tid + 256 * j;          // 0..511
            int r = idx >> 2, c4 = idx & 3;
            av[j] = *(const float4*)(Ab + (size_t)r * K + kt + c4 * 4);
            bv[j] = *(const float4*)(Bb + (size_t)r * K + kt + c4 * 4);
        }
        __syncthreads();   // all warps done reading previous fragments

        // ---- split to tf32 hi/lo, store as fragments ----
#pragma unroll
        for (int j = 0; j < 2; j++) {
            int idx = tid + 256 * j;
            int r = idx >> 2, c4 = idx & 3;
            int h    = c4 >> 1;
            int comp = c4 & 1;
            int rg   = r >> 3;
            int lb   = (r & 7) * 4;
            float va[4] = {av[j].x, av[j].y, av[j].z, av[j].w};
            float vb[4] = {bv[j].x, bv[j].y, bv[j].z, bv[j].w};
#pragma unroll
            for (int q = 0; q < 4; q++) {
                float ahv = tf32r(va[q]);
                float alv = tf32r(va[q] - ahv);
                float bhv = tf32r(vb[q]);
                float blv = tf32r(vb[q] - bhv);
                ((float*)&Ah[h][rg][lb + q])[comp] = ahv;
                ((float*)&Al[h][rg][lb + q])[comp] = alv;
                ((float*)&Bh[h][rg][lb + q])[comp] = bhv;
                ((float*)&Bl[h][rg][lb + q])[comp] = blv;
            }
        }
        __syncthreads();

        // ---- compute: 2 k8 halves x (hh + hl + lh) x 16 mma ----
#pragma unroll
        for (int h = 0; h < 2; h++) {
            uint32_t ah[4][4], al[4][4];
            uint32_t bh[4][2], bl[4][2];
#pragma unroll
            for (int t = 0; t < 4; t++) {
                int g0 = (warpM * 4 + t) * 2;
                float2 p0 = Ah[h][g0][lane];
                float2 p1 = Ah[h][g0 + 1][lane];
                ah[t][0] = __float_as_uint(p0.x); ah[t][1] = __float_as_uint(p1.x);
                ah[t][2] = __float_as_uint(p0.y); ah[t][3] = __float_as_uint(p1.y);
                float2 q0 = Al[h][g0][lane];
                float2 q1 = Al[h][g0 + 1][lane];
                al[t][0] = __float_as_uint(q0.x); al[t][1] = __float_as_uint(q1.x);
                al[t][2] = __float_as_uint(q0.y); al[t][3] = __float_as_uint(q1.y);
            }
#pragma unroll
            for (int u = 0; u < 4; u++) {
                float2 p = Bh[h][warpN * 4 + u][lane];
                bh[u][0] = __float_as_uint(p.x); bh[u][1] = __float_as_uint(p.y);
                float2 q = Bl[h][warpN * 4 + u][lane];
                bl[u][0] = __float_as_uint(q.x); bl[u][1] = __float_as_uint(q.y);
            }
#pragma unroll
            for (int t = 0; t < 4; t++)
#pragma unroll
                for (int u = 0; u < 4; u++) {
                    mma_tf32(acc[t][u], ah[t], bh[u]);
                    mma_tf32(acc[t][u], ah[t], bl[u]);
                    mma_tf32(acc[t][u], al[t], bh[u]);
                }
        }
    }

    const int g = lane >> 2, q2 = (lane & 3) * 2;
#pragma unroll
    for (int t = 0; t < 4; t++) {
        int m0 = bm + warpM * 64 + t * 16 + g;
#pragma unroll
        for (int u = 0; u < 4; u++) {
            int n0 = bn + warpN * 32 + u * 8 + q2;
            *(float2*)(C + (size_t)m0 * N + n0)       = make_float2(acc[t][u][0], acc[t][u][1]);
            *(float2*)(C + (size_t)(m0 + 8) * N + n0) = make_float2(acc[t][u][2], acc[t][u][3]);
        }
    }
}

// =====================================================================
// RoPE-3D applied in place to Q (16 heads) and K (4 groups) of g_qkv.
// =====================================================================
__global__ void rope_kernel(const int* __restrict__ pgt,
                            const int* __restrict__ pgh,
                            const int* __restrict__ pgw) {
    const int token = blockIdx.x;
    const int GH = *pgh, GW = *pgw;
    const int n = token % N_TOK;
    int posv[3];
    posv[0] = n / (GH * GW);
    posv[1] = (n / GW) % GH;
    posv[2] = n % GW;

    const size_t base = (size_t)token * QKV_OUT;
    for (int idx = threadIdx.x; idx < 20 * 48; idx += blockDim.x) {
        const int head = idx / 48;
        const int pi   = idx % 48;
        const int axis = pi >> 4;
        const int p    = pi & 15;
        float freq = powf(10000.0f, -(float)p / 16.0f);
        float ang  = (float)posv[axis] * freq;
        float s, c;
        sincosf(ang, &s, &c);
        int off = (head < 16) ? (head * HEAD_DIM + axis * 32 + 2 * p)
                              : (1536 + (head - 16) * HEAD_DIM + axis * 32 + 2 * p);
        float x0 = g_qkv[base + off];
        float x1 = g_qkv[base + off + 1];
        g_qkv[base + off]     = x0 * c - x1 * s;
        g_qkv[base + off + 1] = x0 * s + x1 * c;
    }
}

// =====================================================================
// K/V -> packed bf16 fragment prepass. One (b, group, tile) per block.
// Output flat layout matches the attention SMEM arrays exactly:
//   K: s = ks*256 + ch*32 + ln   (6 ksteps x 8 chunks x 32 lanes)
//   V: s = ks*384 + ch*32 + ln   (4 ksteps x 12 chunks x 32 lanes)
// =====================================================================
__global__ __launch_bounds__(256) void conv_kv() {
    const int jt = blockIdx.x;        // 0..31
    const int g  = blockIdx.y;        // 0..3
    const int b  = blockIdx.z;        // 0..1
    const int tid = threadIdx.x;

    const int kvtok = b * N_TOK + jt * 64;
    const int koff = 1536 + g * HEAD_DIM;
    const int voff = 1920 + g * HEAD_DIM;
    const size_t obase = (((size_t)(b * QGROUPS + g) * KV_TILES) + jt) * 1536;

    for (int s = tid; s < KFRAG_PER_TILE; s += 256) {
        int ks  = s >> 8;
        int rem = s & 255;
        int ch  = rem >> 5;
        int ln  = rem & 31;
        int n   = ch * 8 + (ln >> 2);
        int k0  = 2 * (ln & 3);
        const float* kp = g_qkv + (size_t)(kvtok + n) * QKV_OUT + koff + 16 * ks + k0;
        float2 p0 = *(const float2*)kp;
        float2 p1 = *(const float2*)(kp + 8);
        uint32_t b0h, b0l, b1h, b1l;
        bsplit2(p0.x, p0.y, b0h, b0l);
        bsplit2(p1.x, p1.y, b1h, b1l);
        g_kfrag[obase + s] = make_uint4(b0h, b1h, b0l, b1l);
    }
    for (int s = tid; s < VFRAG_PER_TILE; s += 256) {
        int ks  = s / 384;
        int rem = s % 384;
        int ch  = rem >> 5;
        int ln  = rem & 31;
        int n   = ch * 8 + (ln >> 2);        // head-dim col
        int k0  = 16 * ks + 2 * (ln & 3);    // kv row within tile
        const float* vp = g_qkv + (size_t)(kvtok + k0) * QKV_OUT + voff + n;
        float a0 = vp[0];
        float a1 = vp[QKV_OUT];
        float a2 = vp[(size_t)8 * QKV_OUT];
        float a3 = vp[(size_t)9 * QKV_OUT];
        uint32_t b0h, b0l, b1h, b1l;
        bsplit2(a0, a1, b0h, b0l);
        bsplit2(a2, a3, b1h, b1l);
        g_vfrag[obase + s] = make_uint4(b0h, b1h, b0l, b1l);
    }
}

// =====================================================================
// Flash attention via mma.sync bf16 (3-term hi/lo split).
// CTA = (64 q-rows, head, batch), 4 warps, warp = 16 q-rows.
// K/V fragments are PRECONVERTED (conv_kv) — the per-tile load is a flat
// coalesced uint4 copy. P fragments straight from S accumulators.
// =====================================================================
__global__ __launch_bounds__(128, 2) void attn_mma() {
    __shared__ uint4 Kf[6][8][32];    // [k16 step][n8 chunk][lane]
    __shared__ uint4 Vf[4][12][32];   // [k16 step][n8 chunk][lane]

    const int tid  = threadIdx.x;
    const int lane = tid & 31;
    const int w    = tid >> 5;        // 0..3
    const int lq   = lane & 3;
    const int lg   = lane >> 2;
    const int qtile = blockIdx.x;     // 0..31
    const int hh    = blockIdx.y;     // 0..15
    const int b     = blockIdx.z;     // 0..1
    const int kvg   = hh >> 2;

    const float scale = rsqrtf((float)HEAD_DIM);
    uint4* KfFlat = &Kf[0][0][0];
    uint4* VfFlat = &Vf[0][0][0];
    const size_t fbase = ((size_t)(b * QGROUPS + kvg) * KV_TILES) * 1536;

    // ---- Q fragments (registers), scale folded in ----
    uint32_t QfH[6][4], QfL[6][4];
    {
        const int qrow = b * N_TOK + qtile * 64 + w * 16 + lg;
        const float* qp0 = g_qkv + (size_t)qrow * QKV_OUT + hh * HEAD_DIM;
        const float* qp1 = qp0 + (size_t)8 * QKV_OUT;
#pragma unroll
        for (int ks = 0; ks < 6; ks++) {
            float2 v0 = *(const float2*)(qp0 + 16 * ks + 2 * lq);
            float2 v1 = *(const float2*)(qp1 + 16 * ks + 2 * lq);
            float2 v2 = *(const float2*)(qp0 + 16 * ks + 2 * lq + 8);
            float2 v3 = *(const float2*)(qp1 + 16 * ks + 2 * lq + 8);
            bsplit2(v0.x * scale, v0.y * scale, QfH[ks][0], QfL[ks][0]);
            bsplit2(v1.x * scale, v1.y * scale, QfH[ks][1], QfL[ks][1]);
            bsplit2(v2.x * scale, v2.y * scale, QfH[ks][2], QfL[ks][2]);
            bsplit2(v3.x * scale, v3.y * scale, QfH[ks][3], QfL[ks][3]);
        }
    }

    float m0 = -INFINITY, m1 = -INFINITY, l0 = 0.f, l1 = 0.f;
    float oacc[12][4];
#pragma unroll
    for (int ch = 0; ch < 12; ch++)
#pragma unroll
        for (int q = 0; q < 4; q++) oacc[ch][q] = 0.f;

    for (int jt = 0; jt < KV_TILES; jt++) {
        __syncthreads();   // previous compute done reading fragments

        // ---- flat coalesced copy of preconverted fragments ----
        const uint4* kfr = g_kfrag + fbase + (size_t)jt * 1536;
        const uint4* vfr = g_vfrag + fbase + (size_t)jt * 1536;
#pragma unroll
        for (int j = 0; j < 12; j++) KfFlat[tid + 128 * j] = kfr[tid + 128 * j];
#pragma unroll
        for (int j = 0; j < 12; j++) VfFlat[tid + 128 * j] = vfr[tid + 128 * j];
        __syncthreads();

        // ---- S = (Q*scale) K^T : 8 chunks x 6 ksteps x 3 terms ----
        float sacc[8][4];
#pragma unroll
        for (int ch = 0; ch < 8; ch++)
#pragma unroll
            for (int q = 0; q < 4; q++) sacc[ch][q] = 0.f;
#pragma unroll
        for (int ks = 0; ks < 6; ks++)
#pragma unroll
            for (int ch = 0; ch < 8; ch++) {
                uint4 kf = Kf[ks][ch][lane];
                mma_bf16(sacc[ch], QfH[ks], kf.x, kf.y);   // hi*hi
                mma_bf16(sacc[ch], QfH[ks], kf.z, kf.w);   // hi*lo
                mma_bf16(sacc[ch], QfL[ks], kf.x, kf.y);   // lo*hi
            }

        // ---- online softmax ----
        float mx0 = -INFINITY, mx1 = -INFINITY;
#pragma unroll
        for (int ch = 0; ch < 8; ch++) {
            mx0 = fmaxf(mx0, fmaxf(sacc[ch][0], sacc[ch][1]));
            mx1 = fmaxf(mx1, fmaxf(sacc[ch][2], sacc[ch][3]));
        }
        mx0 = fmaxf(mx0, __shfl_xor_sync(0xffffffffu, mx0, 1));
        mx0 = fmaxf(mx0, __shfl_xor_sync(0xffffffffu, mx0, 2));
        mx1 = fmaxf(mx1, __shfl_xor_sync(0xffffffffu, mx1, 1));
        mx1 = fmaxf(mx1, __shfl_xor_sync(0xffffffffu, mx1, 2));
        float mn0 = fmaxf(m0, mx0), mn1 = fmaxf(m1, mx1);
        float alpha0 = __expf(m0 - mn0), alpha1 = __expf(m1 - mn1);
        m0 = mn0; m1 = mn1;
        float sum0 = 0.f, sum1 = 0.f;
#pragma unroll
        for (int ch = 0; ch < 8; ch++) {
            sacc[ch][0] = __expf(sacc[ch][0] - mn0);
            sacc[ch][1] = __expf(sacc[ch][1] - mn0);
            sacc[ch][2] = __expf(sacc[ch][2] - mn1);
            sacc[ch][3] = __expf(sacc[ch][3] - mn1);
            sum0 += sacc[ch][0] + sacc[ch][1];
            sum1 += sacc[ch][2] + sacc[ch][3];
        }
        sum0 += __shfl_xor_sync(0xffffffffu, sum0, 1);
        sum0 += __shfl_xor_sync(0xffffffffu, sum0, 2);
        sum1 += __shfl_xor_sync(0xffffffffu, sum1, 1);
        sum1 += __shfl_xor_sync(0xffffffffu, sum1, 2);
        l0 = l0 * alpha0 + sum0;
        l1 = l1 * alpha1 + sum1;
#pragma unroll
        for (int ch = 0; ch < 12; ch++) {
            oacc[ch][0] *= alpha0; oacc[ch][1] *= alpha0;
            oacc[ch][2] *= alpha1; oacc[ch][3] *= alpha1;
        }

        // ---- O += P V : P fragments straight from sacc registers ----
#pragma unroll
        for (int c = 0; c < 4; c++) {
            uint32_t ph[4], pl[4];
            bsplit2(sacc[2 * c][0],     sacc[2 * c][1],     ph[0], pl[0]);
            bsplit2(sacc[2 * c][2],     sacc[2 * c][3],     ph[1], pl[1]);
            bsplit2(sacc[2 * c + 1][0], sacc[2 * c + 1][1], ph[2], pl[2]);
            bsplit2(sacc[2 * c + 1][2], sacc[2 * c + 1][3], ph[3], pl[3]);
#pragma unroll
            for (int ch = 0; ch < 12; ch++) {
                uint4 vf = Vf[c][ch][lane];
                mma_bf16(oacc[ch], ph, vf.x, vf.y);   // hi*hi
                mma_bf16(oacc[ch], ph, vf.z, vf.w);   // hi*lo
                mma_bf16(oacc[ch], pl, vf.x, vf.y);   // lo*hi
            }
        }
    }

    // ---- epilogue: normalize, write [b,n,h,d] ----
    {
        float inv0 = 1.f / l0, inv1 = 1.f / l1;
        const int orow = b * N_TOK + qtile * 64 + w * 16 + lg;
        float* op0 = g_attn + (size_t)orow * D_MODEL + hh * HEAD_DIM;
        float* op1 = op0 + (size_t)8 * D_MODEL;
#pragma unroll
        for (int ch = 0; ch < 12; ch++) {
            *(float2*)(op0 + 8 * ch + 2 * lq) = make_float2(oacc[ch][0] * inv0, oacc[ch][1] * inv0);
            *(float2*)(op1 + 8 * ch + 2 * lq) = make_float2(oacc[ch][2] * inv1, oacc[ch][3] * inv1);
        }
    }
}

// =====================================================================
extern "C" void kernel_launch(void* const* d_in, const int* in_sizes, int n_in,
                              void* d_out, int out_size) {
    const float* x     = (const float*)d_in[0];
    const float* w_qkv = (const float*)d_in[1];
    const float* w_o   = (const float*)d_in[2];
    const int*   gt    = (const int*)d_in[3];
    const int*   gh    = (const int*)d_in[4];
    const int*   gw    = (const int*)d_in[5];
    float* out = (float*)d_out;
    (void)in_sizes; (void)n_in; (void)out_size; (void)gt;

    float *qkv_ptr, *attn_ptr;
    cudaGetSymbolAddress((void**)&qkv_ptr,  g_qkv);
    cudaGetSymbolAddress((void**)&attn_ptr, g_attn);

    // 1) QKV projection: [4096,1536] @ [2304,1536]^T  (mma.sync tf32 3-term)
    gemm_mma<<<dim3(QKV_OUT / BN, BN_TOK / BM), 256>>>(
        x, w_qkv, qkv_ptr, BN_TOK, QKV_OUT, D_MODEL);

    // 2) RoPE-3D in place on Q and K
    rope_kernel<<<BN_TOK, 128>>>(gt, gh, gw);

    // 3) K/V -> packed bf16 fragments (once per KV group, not per head)
    conv_kv<<<dim3(KV_TILES, QGROUPS, B_SZ), 256>>>();

    // 4) GQA flash attention (mma.sync bf16 3-term) -> g_attn [4096,1536]
    attn_mma<<<dim3(N_TOK / 64, NUM_HEADS, B_SZ), 128>>>();

    // 5) Output projection: [4096,1536] @ [1536,1536]^T -> d_out (mma.sync tf32)
    gemm_mma<<<dim3(D_MODEL / BN, BN_TOK / BM), 256>>>(
        attn_ptr, w_o, out, BN_TOK, D_MODEL, D_MODEL);
}